// round 1
// baseline (speedup 1.0000x reference)
#include <cuda_runtime.h>
#include <math.h>

#define H     1024
#define MLPH  4096
#define EXPH  2048
#define NEXP  8
#define NTOK  4096   // max tokens (2*2048)

// ---------------- static device scratch (no allocations allowed) ----------------
__device__ float g_xn[(size_t)NTOK * H];            // LN1(x)
__device__ float g_h1[(size_t)NTOK * MLPH];         // gelu(xn@w1+b1)
__device__ float g_h [(size_t)NTOK * H];            // h1@w2+b2 + x
__device__ float g_x2[(size_t)NTOK * H];            // LN2(h)+h
__device__ float g_he[(size_t)NEXP * NTOK * EXPH];  // expert hidden (per-slot)
__device__ float g_ye[(size_t)NEXP * NTOK * H];     // expert out (per-slot)
__device__ int   g_cnt[NEXP];
__device__ int   g_tok[NEXP * NTOK];
__device__ int   g_slot[2 * NTOK];
__device__ float g_wgt[2 * NTOK];

// ---------------- helpers ----------------
__device__ __forceinline__ unsigned long long pk2(float x) {
    unsigned long long r;
    asm("mov.b64 %0, {%1, %1};" : "=l"(r) : "r"(__float_as_uint(x)));
    return r;
}
__device__ __forceinline__ void fma2(unsigned long long& a, unsigned long long x, unsigned long long y) {
    asm("fma.rn.f32x2 %0, %1, %2, %0;" : "+l"(a) : "l"(x), "l"(y));
}
__device__ __forceinline__ float2 up2(unsigned long long v) {
    unsigned int lo, hi;
    asm("mov.b64 {%0, %1}, %2;" : "=r"(lo), "=r"(hi) : "l"(v));
    return make_float2(__uint_as_float(lo), __uint_as_float(hi));
}
__device__ __forceinline__ float gelu_exact(float x) {
    return 0.5f * x * (1.0f + erff(x * 0.7071067811865476f));
}

// block-wide sum over 256 threads; result broadcast to all threads
__device__ __forceinline__ float block_sum256(float v) {
    __shared__ float s[8];
    __syncthreads();  // protect shared reuse across calls
    #pragma unroll
    for (int o = 16; o; o >>= 1) v += __shfl_down_sync(0xffffffffu, v, o);
    int w = threadIdx.x >> 5, l = threadIdx.x & 31;
    if (l == 0) s[w] = v;
    __syncthreads();
    if (w == 0) {
        float t = (l < 8) ? s[l] : 0.f;
        #pragma unroll
        for (int o = 4; o; o >>= 1) t += __shfl_down_sync(0xffffffffu, t, o);
        if (l == 0) s[0] = t;
    }
    __syncthreads();
    return s[0];
}

// ---------------- LayerNorm (one block of 256 threads per token, H=1024) --------
__global__ void ln_kernel(const float* __restrict__ in, const float* __restrict__ g,
                          const float* __restrict__ b, float* __restrict__ out, int addSelf) {
    int n = blockIdx.x, tid = threadIdx.x;
    int c = tid * 4;
    float4 xv = *(const float4*)&in[(long)n * H + c];
    float mean = block_sum256(xv.x + xv.y + xv.z + xv.w) * (1.0f / H);
    float dx = xv.x - mean, dy = xv.y - mean, dz = xv.z - mean, dw = xv.w - mean;
    float var = block_sum256(dx*dx + dy*dy + dz*dz + dw*dw) * (1.0f / H);
    float rs = rsqrtf(var + 1e-5f);
    float4 gv = *(const float4*)&g[c];
    float4 bv = *(const float4*)&b[c];
    float4 o;
    o.x = dx * rs * gv.x + bv.x;
    o.y = dy * rs * gv.y + bv.y;
    o.z = dz * rs * gv.z + bv.z;
    o.w = dw * rs * gv.w + bv.w;
    if (addSelf) { o.x += xv.x; o.y += xv.y; o.z += xv.z; o.w += xv.w; }
    *(float4*)&out[(long)n * H + c] = o;
}

// ---------------- tiled SGEMM, 128x128x8, 8x8 per thread, f32x2 FMA --------------
// EPI: 0 = gelu(acc + bias), 1 = acc + bias + res, 2 = acc + bias
template<int EPI, bool GATHER, bool EXPERT>
__global__ void __launch_bounds__(256)
gemm_kernel(const float* __restrict__ A0, int lda, long strideA,
            const float* __restrict__ B0, int ldb, long strideB,
            float* __restrict__ C0, int ldc, long strideC,
            const float* __restrict__ bias0, int strideBias,
            const float* __restrict__ res,
            const int* __restrict__ tok, int tokStride,
            const int* __restrict__ cnt,
            int M0, int K) {
    int e = EXPERT ? blockIdx.z : 0;
    int M = EXPERT ? cnt[e] : M0;
    if ((int)(blockIdx.y * 128) >= M) return;   // uniform early-exit (before any sync)

    const float* A = A0 + ((EXPERT && !GATHER) ? (long)e * strideA : 0);
    const float* B = B0 + (EXPERT ? (long)e * strideB : 0);
    float*       C = C0 + (EXPERT ? (long)e * strideC : 0);
    const float* bias = bias0 + (EXPERT ? e * strideBias : 0);

    __shared__ float As[8][128];
    __shared__ float Bs[8][128];

    int tid = threadIdx.x;
    int aRow = tid >> 1,  aCol = (tid & 1) << 2;   // A tile: 128 rows x 8 k
    int bRow = tid >> 5,  bCol = (tid & 31) << 2;  // B tile: 8 k x 128 cols
    int colBase = blockIdx.x * 128;

    int gr = blockIdx.y * 128 + aRow;
    bool aValid = gr < M;
    long arow;
    if (GATHER) arow = aValid ? (long)tok[e * tokStride + gr] : 0;
    else        arow = gr;
    const float* aPtr = A + arow * (long)lda + aCol;
    const float* bPtr = B + (long)bRow * ldb + colBase + bCol;

    int ty = tid >> 4, tx = tid & 15;

    unsigned long long acc[8][4];
    #pragma unroll
    for (int i = 0; i < 8; i++)
        #pragma unroll
        for (int j = 0; j < 4; j++) acc[i][j] = 0ull;

    for (int k0 = 0; k0 < K; k0 += 8) {
        float4 av = make_float4(0.f, 0.f, 0.f, 0.f);
        if (aValid) av = *(const float4*)(aPtr + k0);
        float4 bv = *(const float4*)(bPtr + (long)k0 * ldb);
        As[aCol + 0][aRow] = av.x;
        As[aCol + 1][aRow] = av.y;
        As[aCol + 2][aRow] = av.z;
        As[aCol + 3][aRow] = av.w;
        *(float4*)&Bs[bRow][bCol] = bv;
        __syncthreads();
        #pragma unroll
        for (int kk = 0; kk < 8; kk++) {
            const float* ap = &As[kk][ty * 8];
            float4 aA = *(const float4*)ap;
            float4 aB = *(const float4*)(ap + 4);
            const unsigned long long* bp = (const unsigned long long*)&Bs[kk][tx * 8];
            unsigned long long b0 = bp[0], b1 = bp[1], b2v = bp[2], b3 = bp[3];
            float av8[8] = {aA.x, aA.y, aA.z, aA.w, aB.x, aB.y, aB.z, aB.w};
            #pragma unroll
            for (int i = 0; i < 8; i++) {
                unsigned long long a2 = pk2(av8[i]);
                fma2(acc[i][0], a2, b0);
                fma2(acc[i][1], a2, b1);
                fma2(acc[i][2], a2, b2v);
                fma2(acc[i][3], a2, b3);
            }
        }
        __syncthreads();
    }

    #pragma unroll
    for (int i = 0; i < 8; i++) {
        int grow = blockIdx.y * 128 + ty * 8 + i;
        if (grow >= M) continue;
        float v[8];
        #pragma unroll
        for (int j = 0; j < 4; j++) { float2 f = up2(acc[i][j]); v[2*j] = f.x; v[2*j+1] = f.y; }
        int colb = colBase + tx * 8;
        #pragma unroll
        for (int m = 0; m < 8; m++) {
            int col = colb + m;
            float xv = v[m] + bias[col];
            if (EPI == 0)       xv = gelu_exact(xv);
            else if (EPI == 1)  xv += res[(long)grow * ldc + col];
            v[m] = xv;
        }
        float4* cp = (float4*)&C[(long)grow * ldc + colb];
        cp[0] = make_float4(v[0], v[1], v[2], v[3]);
        cp[1] = make_float4(v[4], v[5], v[6], v[7]);
    }
}

// ---------------- router: one warp per token ----------------
__global__ void router_kernel(const float* __restrict__ x2, const float* __restrict__ rw,
                              int* __restrict__ cnt, int* __restrict__ tok,
                              int* __restrict__ slot, float* __restrict__ wgt, int NT) {
    int warp = threadIdx.x >> 5, lane = threadIdx.x & 31;
    int n = blockIdx.x * 4 + warp;
    if (n >= NT) return;
    float acc[NEXP];
    #pragma unroll
    for (int e = 0; e < NEXP; e++) acc[e] = 0.f;
    const float* xr = x2 + (long)n * H;
    for (int h = lane; h < H; h += 32) {
        float xv = xr[h];
        const float4* r = (const float4*)&rw[h * NEXP];
        float4 r0 = r[0], r1 = r[1];
        acc[0] += xv * r0.x; acc[1] += xv * r0.y; acc[2] += xv * r0.z; acc[3] += xv * r0.w;
        acc[4] += xv * r1.x; acc[5] += xv * r1.y; acc[6] += xv * r1.z; acc[7] += xv * r1.w;
    }
    #pragma unroll
    for (int e = 0; e < NEXP; e++)
        #pragma unroll
        for (int o = 16; o; o >>= 1) acc[e] += __shfl_down_sync(0xffffffffu, acc[e], o);
    if (lane == 0) {
        // top-2 by logit (same order as softmax probs); ties -> lowest index (matches top_k)
        int i1 = 0;
        #pragma unroll
        for (int e = 1; e < NEXP; e++) if (acc[e] > acc[i1]) i1 = e;
        int i2 = (i1 == 0) ? 1 : 0;
        #pragma unroll
        for (int e = 0; e < NEXP; e++) { if (e == i1 || e == i2) continue; if (acc[e] > acc[i2]) i2 = e; }
        // normalized top-2 weights: p1/(p1+p2) = 1/(1+exp(l2-l1))
        float d  = expf(acc[i2] - acc[i1]);
        float w1 = 1.0f / (1.0f + d);
        float w2 = d / (1.0f + d);
        int p1 = atomicAdd(&cnt[i1], 1);
        int p2 = atomicAdd(&cnt[i2], 1);
        tok[i1 * NT + p1] = n;
        tok[i2 * NT + p2] = n;
        slot[2*n]   = i1 * NT + p1;  wgt[2*n]   = w1;
        slot[2*n+1] = i2 * NT + p2;  wgt[2*n+1] = w2;
    }
}

// ---------------- combine top-2 expert outputs + final LayerNorm ----------------
__global__ void combine_ln_kernel(const float* __restrict__ ye, const int* __restrict__ slot,
                                  const float* __restrict__ wgt, const float* __restrict__ g,
                                  const float* __restrict__ b, float* __restrict__ out) {
    int n = blockIdx.x, tid = threadIdx.x;
    int s0 = slot[2*n], s1 = slot[2*n+1];
    float w0 = wgt[2*n], w1 = wgt[2*n+1];
    int c = tid * 4;
    float4 y0 = *(const float4*)&ye[(long)s0 * H + c];
    float4 y1 = *(const float4*)&ye[(long)s1 * H + c];
    float4 v;
    v.x = w0*y0.x + w1*y1.x; v.y = w0*y0.y + w1*y1.y;
    v.z = w0*y0.z + w1*y1.z; v.w = w0*y0.w + w1*y1.w;
    float mean = block_sum256(v.x + v.y + v.z + v.w) * (1.0f / H);
    float dx = v.x - mean, dy = v.y - mean, dz = v.z - mean, dw = v.w - mean;
    float var = block_sum256(dx*dx + dy*dy + dz*dz + dw*dw) * (1.0f / H);
    float rs = rsqrtf(var + 1e-5f);
    float4 gv = *(const float4*)&g[c];
    float4 bv = *(const float4*)&b[c];
    float4 o;
    o.x = dx * rs * gv.x + bv.x;
    o.y = dy * rs * gv.y + bv.y;
    o.z = dz * rs * gv.z + bv.z;
    o.w = dw * rs * gv.w + bv.w;
    *(float4*)&out[(long)n * H + c] = o;
}

__global__ void aux_kernel(const int* __restrict__ cnt, float* __restrict__ out,
                           long auxIdx, float invTotal) {
    float a = 0.f;
    #pragma unroll
    for (int e = 0; e < NEXP; e++) {
        float load = (float)cnt[e] * invTotal;
        a += load * logf(load + 1e-9f);
    }
    out[auxIdx] = 0.01f * a;
}

__global__ void reset_kernel(int* cnt) { if (threadIdx.x < NEXP) cnt[threadIdx.x] = 0; }

// ---------------- launch ----------------
extern "C" void kernel_launch(void* const* d_in, const int* in_sizes, int n_in,
                              void* d_out, int out_size) {
    const float* x    = (const float*)d_in[0];
    const float* ln1g = (const float*)d_in[1];
    const float* ln1b = (const float*)d_in[2];
    const float* ln2g = (const float*)d_in[3];
    const float* ln2b = (const float*)d_in[4];
    const float* w1   = (const float*)d_in[5];
    const float* b1   = (const float*)d_in[6];
    const float* w2   = (const float*)d_in[7];
    const float* b2   = (const float*)d_in[8];
    const float* rw   = (const float*)d_in[9];
    const float* ew1  = (const float*)d_in[10];
    const float* eb1  = (const float*)d_in[11];
    const float* ew2  = (const float*)d_in[12];
    const float* eb2  = (const float*)d_in[13];
    const float* lnfg = (const float*)d_in[14];
    const float* lnfb = (const float*)d_in[15];
    float* out = (float*)d_out;

    int NT = in_sizes[0] / H;   // 4096

    float *xn, *h1, *hh, *x2, *he, *ye, *wgt;
    int *cnt, *tok, *slot;
    cudaGetSymbolAddress((void**)&xn,   g_xn);
    cudaGetSymbolAddress((void**)&h1,   g_h1);
    cudaGetSymbolAddress((void**)&hh,   g_h);
    cudaGetSymbolAddress((void**)&x2,   g_x2);
    cudaGetSymbolAddress((void**)&he,   g_he);
    cudaGetSymbolAddress((void**)&ye,   g_ye);
    cudaGetSymbolAddress((void**)&wgt,  g_wgt);
    cudaGetSymbolAddress((void**)&cnt,  g_cnt);
    cudaGetSymbolAddress((void**)&tok,  g_tok);
    cudaGetSymbolAddress((void**)&slot, g_slot);

    reset_kernel<<<1, 32>>>(cnt);

    // ResMLP block
    ln_kernel<<<NT, 256>>>(x, ln1g, ln1b, xn, 0);
    gemm_kernel<0, false, false><<<dim3(MLPH/128, NT/128), 256>>>(
        xn, H, 0,  w1, MLPH, 0,  h1, MLPH, 0,  b1, 0,
        nullptr, nullptr, 0, nullptr, NT, H);
    gemm_kernel<1, false, false><<<dim3(H/128, NT/128), 256>>>(
        h1, MLPH, 0,  w2, H, 0,  hh, H, 0,  b2, 0,
        x, nullptr, 0, nullptr, NT, MLPH);
    ln_kernel<<<NT, 256>>>(hh, ln2g, ln2b, x2, 1);

    // MoE: router + sparse top-2 dispatch
    router_kernel<<<(NT + 3) / 4, 128>>>(x2, rw, cnt, tok, slot, wgt, NT);
    gemm_kernel<0, true, true><<<dim3(EXPH/128, NT/128, NEXP), 256>>>(
        x2, H, 0,  ew1, EXPH, (long)H * EXPH,  he, EXPH, (long)NT * EXPH,
        eb1, EXPH, nullptr, tok, NT, cnt, NT, H);
    gemm_kernel<2, false, true><<<dim3(H/128, NT/128, NEXP), 256>>>(
        he, EXPH, (long)NT * EXPH,  ew2, H, (long)EXPH * H,  ye, H, (long)NT * H,
        eb2, H, nullptr, nullptr, 0, cnt, NT, EXPH);

    // combine + final LN + aux loss
    combine_ln_kernel<<<NT, 256>>>(ye, slot, wgt, lnfg, lnfb, out);
    if (out_size > NT * H)
        aux_kernel<<<1, 1>>>(cnt, out, (long)NT * H, 1.0f / (2.0f * NT));
}

// round 4
// speedup vs baseline: 3.9012x; 3.9012x over previous
#include <cuda_runtime.h>
#include <math.h>
#include <stdint.h>

#define H     1024
#define MLPH  4096
#define EXPH  2048
#define NEXP  8
#define NTOK  4096

// tcgen05 is an "a"-suffix feature: real body only in the sm_103a/sm_100a
// specific device pass (and host pass); empty stub for generic compute_103 PTX.
#if !defined(__CUDA_ARCH__) || defined(__CUDA_ARCH_FEAT_SM103_ALL) || defined(__CUDA_ARCH_FEAT_SM100_ALL) || defined(__CUDA_ARCH_SPECIFIC__)
#define TC_OK 1
#else
#define TC_OK 0
#endif

// ---------------- static device scratch ----------------
__device__ float g_xn[(size_t)NTOK * H];
__device__ float g_h1[(size_t)NTOK * MLPH];
__device__ float g_h [(size_t)NTOK * H];
__device__ float g_x2[(size_t)NTOK * H];
__device__ float g_he[(size_t)NEXP * NTOK * EXPH];
__device__ float g_ye[(size_t)NEXP * NTOK * H];
__device__ int   g_cnt[NEXP];
__device__ int   g_tok[NEXP * NTOK];
__device__ int   g_slot[2 * NTOK];
__device__ float g_wgt[2 * NTOK];

// ---------------- PTX helpers ----------------
__device__ __forceinline__ uint32_t smem_u32(const void* p) {
    uint32_t a;
    asm("{ .reg .u64 t; cvta.to.shared.u64 t, %1; cvt.u32.u64 %0, t; }" : "=r"(a) : "l"(p));
    return a;
}
__device__ __forceinline__ uint32_t elect_one_pred() {
    uint32_t p;
    asm volatile("{\n\t.reg .pred q;\n\telect.sync _|q, 0xFFFFFFFF;\n\tselp.b32 %0, 1, 0, q;\n\t}" : "=r"(p));
    return p;
}
#define MBARRIER_INIT(addr, cnt) \
    asm volatile("mbarrier.init.shared.b64 [%0], %1;" :: "r"((uint32_t)(addr)), "r"((uint32_t)(cnt)) : "memory")
#define MBARRIER_WAIT_PARITY(addr, par) do { \
    uint32_t _m = (uint32_t)(addr), _p = (uint32_t)(par), _d; \
    asm volatile("{\n\t.reg .pred p;\n\tmbarrier.try_wait.parity.acquire.cta.shared::cta.b64 p, [%1], %2;\n\tselp.b32 %0, 1, 0, p;\n\t}" \
        : "=r"(_d) : "r"(_m), "r"(_p) : "memory"); \
    if (!_d) { \
        asm volatile("{\n\t.reg .pred P1;\n\tWL_%=:\n\tmbarrier.try_wait.parity.acquire.cta.shared::cta.b64 P1, [%0], %1, 0x989680;\n\t@P1 bra.uni WD_%=;\n\tbra.uni WL_%=;\n\tWD_%=:\n\t}" \
            :: "r"(_m), "r"(_p) : "memory"); \
    } } while (0)

#if TC_OK
#define TCGEN05_ALLOC(saddr, n) \
    asm volatile("tcgen05.alloc.cta_group::1.sync.aligned.shared::cta.b32 [%0], %1;" :: "r"((uint32_t)(saddr)), "r"((uint32_t)(n)) : "memory")
#define TCGEN05_RELINQ() \
    asm volatile("tcgen05.relinquish_alloc_permit.cta_group::1.sync.aligned;")
#define TCGEN05_DEALLOC(taddr, n) \
    asm volatile("tcgen05.dealloc.cta_group::1.sync.aligned.b32 %0, %1;" :: "r"(taddr), "r"((uint32_t)(n)))
#define TCGEN05_COMMIT(mbar) \
    asm volatile("tcgen05.commit.cta_group::1.mbarrier::arrive::one.shared::cluster.b64 [%0];" :: "r"((uint32_t)(mbar)) : "memory")
#define TCGEN05_WAIT_LD()  asm volatile("tcgen05.wait::ld.sync.aligned;" ::: "memory")
#define TCGEN05_FENCE_AFTER()  asm volatile("tcgen05.fence::after_thread_sync;" ::: "memory")
#define TCGEN05_FENCE_BEFORE() asm volatile("tcgen05.fence::before_thread_sync;" ::: "memory")
#define TCGEN05_LD_X32(r, ta) \
    asm volatile("tcgen05.ld.sync.aligned.32x32b.x32.b32 " \
        "{%0, %1, %2, %3, %4, %5, %6, %7, %8, %9, %10, %11, %12, %13, %14, %15, " \
        " %16, %17, %18, %19, %20, %21, %22, %23, %24, %25, %26, %27, %28, %29, %30, %31}, [%32];" \
        : "=r"((r)[0]),  "=r"((r)[1]),  "=r"((r)[2]),  "=r"((r)[3]), \
          "=r"((r)[4]),  "=r"((r)[5]),  "=r"((r)[6]),  "=r"((r)[7]), \
          "=r"((r)[8]),  "=r"((r)[9]),  "=r"((r)[10]), "=r"((r)[11]), \
          "=r"((r)[12]), "=r"((r)[13]), "=r"((r)[14]), "=r"((r)[15]), \
          "=r"((r)[16]), "=r"((r)[17]), "=r"((r)[18]), "=r"((r)[19]), \
          "=r"((r)[20]), "=r"((r)[21]), "=r"((r)[22]), "=r"((r)[23]), \
          "=r"((r)[24]), "=r"((r)[25]), "=r"((r)[26]), "=r"((r)[27]), \
          "=r"((r)[28]), "=r"((r)[29]), "=r"((r)[30]), "=r"((r)[31]) \
        : "r"(ta))

__device__ __forceinline__ void mma_tf32(uint32_t d, uint64_t ad, uint64_t bd, uint32_t idesc, bool acc) {
    uint32_t en = acc ? 1u : 0u, z = 0u;
    asm volatile("{\n\t.reg .pred p;\n\tsetp.ne.u32 p, %5, 0;\n\t"
        "tcgen05.mma.cta_group::1.kind::tf32 [%0], %1, %2, %3, {%4,%4,%4,%4}, p;\n\t}"
        :: "r"(d), "l"(ad), "l"(bd), "r"(idesc), "r"(z), "r"(en) : "memory");
}
#endif // TC_OK

static __device__ __forceinline__ uint64_t make_desc(uint32_t addr) {
    // K-major SW128: layout=2, version=1, SBO=64, LBO=1
    uint64_t d = (uint64_t(2) << 61) | (uint64_t(1) << 46) | (uint64_t(64) << 32) | (uint64_t(1) << 16);
    return d | ((uint64_t)(addr >> 4) & 0x3FFF);
}
__device__ __forceinline__ uint32_t sw128(uint32_t o) { return o ^ ((o >> 3) & 0x70); }
__device__ __forceinline__ float to_tf32(float x) {
    float r; asm("cvt.rna.tf32.f32 %0, %1;" : "=f"(r) : "f"(x)); return r;
}
__device__ __forceinline__ float gelu_exact(float x) {
    return 0.5f * x * (1.0f + erff(x * 0.7071067811865476f));
}
// 4x4 transpose within quad of lanes; sub = lane & 3
__device__ __forceinline__ void quad_transpose(float v[4], int sub) {
    float x = (sub & 1) ? v[0] : v[1];
    float y = (sub & 1) ? v[2] : v[3];
    x = __shfl_xor_sync(0xffffffffu, x, 1);
    y = __shfl_xor_sync(0xffffffffu, y, 1);
    if (sub & 1) { v[0] = x; v[2] = y; } else { v[1] = x; v[3] = y; }
    float p = (sub & 2) ? v[0] : v[2];
    float q = (sub & 2) ? v[1] : v[3];
    p = __shfl_xor_sync(0xffffffffu, p, 2);
    q = __shfl_xor_sync(0xffffffffu, q, 2);
    if (sub & 2) { v[0] = p; v[1] = q; } else { v[2] = p; v[3] = q; }
}

// ---------------- smem map (dynamic, 99328 B) ----------------
// [0:4)   tmem ptr    [8:24) mbar[2]
// [1024 + s*16384)  A stage s: 128 rows x 32 k fp32 (SW128)
// [33792 + s*32768) B stage s: 256 rows x 32 k fp32 (SW128)
#define SMEM_BYTES 99328

// ---------------- tcgen05 tf32 GEMM: tile 128(M) x 256(N), K-stage 32 --------
// EPI: 0 = gelu(acc+bias), 1 = acc+bias+res, 2 = acc+bias
template<int EPI, bool GATHER, bool EXPERT>
__global__ void __launch_bounds__(256, 2)
mma_gemm(const float* __restrict__ A0, int lda, long strideA,
         const float* __restrict__ B0, int ldb, long strideB,
         float* __restrict__ C0, int ldc, long strideC,
         const float* __restrict__ bias0, int strideBias,
         const float* __restrict__ res,
         const int* __restrict__ tok, int tokStride,
         const int* __restrict__ cnt, int M0, int K) {
#if !TC_OK
    // generic-arch compile pass only; never executed (driver loads sm_103a cubin)
    return;
#else
    int e = EXPERT ? blockIdx.z : 0;
    int M = EXPERT ? cnt[e] : M0;
    int mBase = blockIdx.y * 128;
    if (mBase >= M) return;
    int colBase = blockIdx.x * 256;

    extern __shared__ char smem[];
    uint32_t sb = smem_u32(smem);
    int tid = threadIdx.x, wid = tid >> 5, lane = tid & 31;

    if (wid == 0) { TCGEN05_ALLOC(sb, 256); TCGEN05_RELINQ(); }
    if (tid == 0) { MBARRIER_INIT(sb + 8, 1); MBARRIER_INIT(sb + 16, 1); }
    __syncthreads();
    uint32_t tmem;
    asm volatile("ld.shared.b32 %0, [%1];" : "=r"(tmem) : "r"(sb));

    const float* A = A0 + ((EXPERT && !GATHER) ? (long)e * strideA : 0);
    const float* B = B0 + (EXPERT ? (long)e * strideB : 0);
    float*       C = C0 + (EXPERT ? (long)e * strideC : 0);
    const float* bias = bias0 + (EXPERT ? e * strideBias : 0);

    // --- A-tile per-thread mapping: 4 x (row, kq) cells ---
    const float* aPtr[4]; bool aOk[4]; uint32_t aSoff[4];
    #pragma unroll
    for (int i = 0; i < 4; i++) {
        int idx = tid + 256 * i;
        int r = idx >> 3, kq = idx & 7;
        int grow = mBase + r;
        aOk[i] = grow < M;
        long rr = 0;
        if (aOk[i]) rr = GATHER ? (long)tok[e * tokStride + grow] : (long)grow;
        aPtr[i] = A + rr * (long)lda + kq * 4;
        aSoff[i] = sw128((uint32_t)(r * 128 + kq * 16));
    }
    // --- B-tile per-thread mapping (transpose [K,N]->[N,K] in registers) ---
    int q = lane >> 2, sub = lane & 3;
    int nn = (wid * 8 + q) * 4 + sub;                         // smem row after transpose
    const float* bPtr = B + (long)sub * ldb + (colBase + (wid * 8 + q) * 4);
    uint32_t bSoff[8];
    #pragma unroll
    for (int i = 0; i < 8; i++) bSoff[i] = sw128((uint32_t)(nn * 128 + i * 16));

    const uint32_t aOffBase[2] = { 1024u, 1024u + 16384u };
    const uint32_t bOffBase[2] = { 33792u, 33792u + 32768u };
    uint64_t aDesc[2], bDesc[2];
    #pragma unroll
    for (int s = 0; s < 2; s++) { aDesc[s] = make_desc(sb + aOffBase[s]); bDesc[s] = make_desc(sb + bOffBase[s]); }

    // idesc: dtype F32=1 [4:5], atype TF32=2 [7:9], btype TF32=2 [10:12],
    //        N/8 [17:22], M/16 [24:28]
    const uint32_t idesc = (1u << 4) | (2u << 7) | (2u << 10) | ((256u / 8) << 17) | ((128u / 16) << 24);

    auto loadA = [&](int kt, int s) {
        #pragma unroll
        for (int i = 0; i < 4; i++) {
            float4 v = make_float4(0.f, 0.f, 0.f, 0.f);
            if (aOk[i]) v = *(const float4*)(aPtr[i] + kt * 32);
            v.x = to_tf32(v.x); v.y = to_tf32(v.y); v.z = to_tf32(v.z); v.w = to_tf32(v.w);
            *(float4*)(smem + aOffBase[s] + aSoff[i]) = v;
        }
    };
    auto loadB = [&](int kt, int s) {
        #pragma unroll
        for (int i = 0; i < 8; i++) {
            float4 v = *(const float4*)(bPtr + (long)(kt * 32 + 4 * i) * ldb);
            float t[4] = { to_tf32(v.x), to_tf32(v.y), to_tf32(v.z), to_tf32(v.w) };
            quad_transpose(t, sub);
            *(float4*)(smem + bOffBase[s] + bSoff[i]) = make_float4(t[0], t[1], t[2], t[3]);
        }
    };

    loadA(0, 0); loadB(0, 0);
    asm volatile("fence.proxy.async.shared::cta;" ::: "memory");
    __syncthreads();

    int T = K / 32;
    int ph0 = 0, ph1 = 0;
    for (int t = 0; t < T; t++) {
        int b = t & 1;
        if (wid == 0 && elect_one_pred()) {
            #pragma unroll
            for (int k = 0; k < 4; k++)
                mma_tf32(tmem, aDesc[b] + k * 2, bDesc[b] + k * 2, idesc, (t > 0) || (k > 0));
            TCGEN05_COMMIT(sb + 8 + b * 8);
        }
        if (t + 1 < T) {
            int nb = b ^ 1;
            if (t >= 1) {
                // wait for the MMA that last read buffer nb before overwriting it
                if (nb) { MBARRIER_WAIT_PARITY(sb + 16, ph1); ph1 ^= 1; }
                else    { MBARRIER_WAIT_PARITY(sb + 8,  ph0); ph0 ^= 1; }
            }
            loadA(t + 1, nb); loadB(t + 1, nb);
            asm volatile("fence.proxy.async.shared::cta;" ::: "memory");
            __syncthreads();
        }
    }
    {
        // final commit tracks ALL prior tcgen05 ops -> one wait suffices
        int lb = (T - 1) & 1;
        if (lb) { MBARRIER_WAIT_PARITY(sb + 16, ph1); }
        else    { MBARRIER_WAIT_PARITY(sb + 8,  ph0); }
    }
    TCGEN05_FENCE_AFTER();

    // --- epilogue: warp (wid&3) -> TMEM lane group, (wid>>2) -> column half ---
    int wq = wid & 3, wh = wid >> 2;
    int row = mBase + wq * 32 + lane;
    bool rOk = row < M;
    float* crow = C + (long)row * ldc;
    const float* rrow = res + (long)row * ldc;
    #pragma unroll
    for (int c = 0; c < 4; c++) {
        int col0 = wh * 128 + c * 32;
        uint32_t r[32];
        TCGEN05_LD_X32(r, tmem + col0);
        TCGEN05_WAIT_LD();
        if (rOk) {
            #pragma unroll
            for (int j = 0; j < 32; j += 4) {
                int g = colBase + col0 + j;
                float4 o;
                o.x = __uint_as_float(r[j + 0]) + bias[g + 0];
                o.y = __uint_as_float(r[j + 1]) + bias[g + 1];
                o.z = __uint_as_float(r[j + 2]) + bias[g + 2];
                o.w = __uint_as_float(r[j + 3]) + bias[g + 3];
                if (EPI == 0) {
                    o.x = gelu_exact(o.x); o.y = gelu_exact(o.y);
                    o.z = gelu_exact(o.z); o.w = gelu_exact(o.w);
                } else if (EPI == 1) {
                    o.x += rrow[g + 0]; o.y += rrow[g + 1];
                    o.z += rrow[g + 2]; o.w += rrow[g + 3];
                }
                *(float4*)(crow + g) = o;
            }
        }
    }
    TCGEN05_FENCE_BEFORE();
    __syncthreads();
    if (wid == 0) TCGEN05_DEALLOC(tmem, 256);
#endif // TC_OK
}

// ---------------- block reduce ----------------
__device__ __forceinline__ float block_sum256(float v) {
    __shared__ float s[8];
    __syncthreads();
    #pragma unroll
    for (int o = 16; o; o >>= 1) v += __shfl_down_sync(0xffffffffu, v, o);
    int w = threadIdx.x >> 5, l = threadIdx.x & 31;
    if (l == 0) s[w] = v;
    __syncthreads();
    if (w == 0) {
        float t = (l < 8) ? s[l] : 0.f;
        #pragma unroll
        for (int o = 4; o; o >>= 1) t += __shfl_down_sync(0xffffffffu, t, o);
        if (l == 0) s[0] = t;
    }
    __syncthreads();
    return s[0];
}

// ---------------- LayerNorm ----------------
__global__ void ln_kernel(const float* __restrict__ in, const float* __restrict__ g,
                          const float* __restrict__ b, float* __restrict__ out, int addSelf) {
    int n = blockIdx.x, tid = threadIdx.x;
    int c = tid * 4;
    float4 xv = *(const float4*)&in[(long)n * H + c];
    float mean = block_sum256(xv.x + xv.y + xv.z + xv.w) * (1.0f / H);
    float dx = xv.x - mean, dy = xv.y - mean, dz = xv.z - mean, dw = xv.w - mean;
    float var = block_sum256(dx*dx + dy*dy + dz*dz + dw*dw) * (1.0f / H);
    float rs = rsqrtf(var + 1e-5f);
    float4 gv = *(const float4*)&g[c];
    float4 bv = *(const float4*)&b[c];
    float4 o;
    o.x = dx * rs * gv.x + bv.x;
    o.y = dy * rs * gv.y + bv.y;
    o.z = dz * rs * gv.z + bv.z;
    o.w = dw * rs * gv.w + bv.w;
    if (addSelf) { o.x += xv.x; o.y += xv.y; o.z += xv.z; o.w += xv.w; }
    *(float4*)&out[(long)n * H + c] = o;
}

// ---------------- router ----------------
__global__ void router_kernel(const float* __restrict__ x2, const float* __restrict__ rw,
                              int* __restrict__ cnt, int* __restrict__ tok,
                              int* __restrict__ slot, float* __restrict__ wgt, int NT) {
    int warp = threadIdx.x >> 5, lane = threadIdx.x & 31;
    int n = blockIdx.x * 4 + warp;
    if (n >= NT) return;
    float acc[NEXP];
    #pragma unroll
    for (int e = 0; e < NEXP; e++) acc[e] = 0.f;
    const float* xr = x2 + (long)n * H;
    for (int h = lane; h < H; h += 32) {
        float xv = xr[h];
        const float4* r = (const float4*)&rw[h * NEXP];
        float4 r0 = r[0], r1 = r[1];
        acc[0] += xv * r0.x; acc[1] += xv * r0.y; acc[2] += xv * r0.z; acc[3] += xv * r0.w;
        acc[4] += xv * r1.x; acc[5] += xv * r1.y; acc[6] += xv * r1.z; acc[7] += xv * r1.w;
    }
    #pragma unroll
    for (int e = 0; e < NEXP; e++)
        #pragma unroll
        for (int o = 16; o; o >>= 1) acc[e] += __shfl_down_sync(0xffffffffu, acc[e], o);
    if (lane == 0) {
        int i1 = 0;
        #pragma unroll
        for (int e = 1; e < NEXP; e++) if (acc[e] > acc[i1]) i1 = e;
        int i2 = (i1 == 0) ? 1 : 0;
        #pragma unroll
        for (int e = 0; e < NEXP; e++) { if (e == i1 || e == i2) continue; if (acc[e] > acc[i2]) i2 = e; }
        float d  = expf(acc[i2] - acc[i1]);
        float w1 = 1.0f / (1.0f + d);
        float w2 = d / (1.0f + d);
        int p1 = atomicAdd(&cnt[i1], 1);
        int p2 = atomicAdd(&cnt[i2], 1);
        tok[i1 * NT + p1] = n;
        tok[i2 * NT + p2] = n;
        slot[2*n]   = i1 * NT + p1;  wgt[2*n]   = w1;
        slot[2*n+1] = i2 * NT + p2;  wgt[2*n+1] = w2;
    }
}

// ---------------- combine + final LN ----------------
__global__ void combine_ln_kernel(const float* __restrict__ ye, const int* __restrict__ slot,
                                  const float* __restrict__ wgt, const float* __restrict__ g,
                                  const float* __restrict__ b, float* __restrict__ out) {
    int n = blockIdx.x, tid = threadIdx.x;
    int s0 = slot[2*n], s1 = slot[2*n+1];
    float w0 = wgt[2*n], w1 = wgt[2*n+1];
    int c = tid * 4;
    float4 y0 = *(const float4*)&ye[(long)s0 * H + c];
    float4 y1 = *(const float4*)&ye[(long)s1 * H + c];
    float4 v;
    v.x = w0*y0.x + w1*y1.x; v.y = w0*y0.y + w1*y1.y;
    v.z = w0*y0.z + w1*y1.z; v.w = w0*y0.w + w1*y1.w;
    float mean = block_sum256(v.x + v.y + v.z + v.w) * (1.0f / H);
    float dx = v.x - mean, dy = v.y - mean, dz = v.z - mean, dw = v.w - mean;
    float var = block_sum256(dx*dx + dy*dy + dz*dz + dw*dw) * (1.0f / H);
    float rs = rsqrtf(var + 1e-5f);
    float4 gv = *(const float4*)&g[c];
    float4 bv = *(const float4*)&b[c];
    float4 o;
    o.x = dx * rs * gv.x + bv.x;
    o.y = dy * rs * gv.y + bv.y;
    o.z = dz * rs * gv.z + bv.z;
    o.w = dw * rs * gv.w + bv.w;
    *(float4*)&out[(long)n * H + c] = o;
}

__global__ void aux_kernel(const int* __restrict__ cnt, float* __restrict__ out,
                           long auxIdx, float invTotal) {
    float a = 0.f;
    #pragma unroll
    for (int e = 0; e < NEXP; e++) {
        float load = (float)cnt[e] * invTotal;
        a += load * logf(load + 1e-9f);
    }
    out[auxIdx] = 0.01f * a;
}

__global__ void reset_kernel(int* cnt) { if (threadIdx.x < NEXP) cnt[threadIdx.x] = 0; }

// ---------------- launch ----------------
extern "C" void kernel_launch(void* const* d_in, const int* in_sizes, int n_in,
                              void* d_out, int out_size) {
    const float* x    = (const float*)d_in[0];
    const float* ln1g = (const float*)d_in[1];
    const float* ln1b = (const float*)d_in[2];
    const float* ln2g = (const float*)d_in[3];
    const float* ln2b = (const float*)d_in[4];
    const float* w1   = (const float*)d_in[5];
    const float* b1   = (const float*)d_in[6];
    const float* w2   = (const float*)d_in[7];
    const float* b2   = (const float*)d_in[8];
    const float* rw   = (const float*)d_in[9];
    const float* ew1  = (const float*)d_in[10];
    const float* eb1  = (const float*)d_in[11];
    const float* ew2  = (const float*)d_in[12];
    const float* eb2  = (const float*)d_in[13];
    const float* lnfg = (const float*)d_in[14];
    const float* lnfb = (const float*)d_in[15];
    float* out = (float*)d_out;

    int NT = in_sizes[0] / H;   // 4096

    float *xn, *h1, *hh, *x2, *he, *ye, *wgt;
    int *cnt, *tok, *slot;
    cudaGetSymbolAddress((void**)&xn,   g_xn);
    cudaGetSymbolAddress((void**)&h1,   g_h1);
    cudaGetSymbolAddress((void**)&hh,   g_h);
    cudaGetSymbolAddress((void**)&x2,   g_x2);
    cudaGetSymbolAddress((void**)&he,   g_he);
    cudaGetSymbolAddress((void**)&ye,   g_ye);
    cudaGetSymbolAddress((void**)&wgt,  g_wgt);
    cudaGetSymbolAddress((void**)&cnt,  g_cnt);
    cudaGetSymbolAddress((void**)&tok,  g_tok);
    cudaGetSymbolAddress((void**)&slot, g_slot);

    // idempotent, capture-safe; no static guards (harness rule)
    cudaFuncSetAttribute(mma_gemm<0, false, false>, cudaFuncAttributeMaxDynamicSharedMemorySize, SMEM_BYTES);
    cudaFuncSetAttribute(mma_gemm<1, false, false>, cudaFuncAttributeMaxDynamicSharedMemorySize, SMEM_BYTES);
    cudaFuncSetAttribute(mma_gemm<0, true,  true >, cudaFuncAttributeMaxDynamicSharedMemorySize, SMEM_BYTES);
    cudaFuncSetAttribute(mma_gemm<2, false, true >, cudaFuncAttributeMaxDynamicSharedMemorySize, SMEM_BYTES);

    reset_kernel<<<1, 32>>>(cnt);

    // ResMLP block
    ln_kernel<<<NT, 256>>>(x, ln1g, ln1b, xn, 0);
    mma_gemm<0, false, false><<<dim3(MLPH/256, NT/128), 256, SMEM_BYTES>>>(
        xn, H, 0,  w1, MLPH, 0,  h1, MLPH, 0,  b1, 0,
        nullptr, nullptr, 0, nullptr, NT, H);
    mma_gemm<1, false, false><<<dim3(H/256, NT/128), 256, SMEM_BYTES>>>(
        h1, MLPH, 0,  w2, H, 0,  hh, H, 0,  b2, 0,
        x, nullptr, 0, nullptr, NT, MLPH);
    ln_kernel<<<NT, 256>>>(hh, ln2g, ln2b, x2, 1);

    // MoE
    router_kernel<<<(NT + 3) / 4, 128>>>(x2, rw, cnt, tok, slot, wgt, NT);
    mma_gemm<0, true, true><<<dim3(EXPH/256, NT/128, NEXP), 256, SMEM_BYTES>>>(
        x2, H, 0,  ew1, EXPH, (long)H * EXPH,  he, EXPH, (long)NT * EXPH,
        eb1, EXPH, nullptr, tok, NT, cnt, NT, H);
    mma_gemm<2, false, true><<<dim3(H/256, NT/128, NEXP), 256, SMEM_BYTES>>>(
        he, EXPH, (long)NT * EXPH,  ew2, H, (long)EXPH * H,  ye, H, (long)NT * H,
        eb2, H, nullptr, nullptr, 0, cnt, NT, EXPH);

    // combine + final LN + aux
    combine_ln_kernel<<<NT, 256>>>(ye, slot, wgt, lnfg, lnfb, out);
    if (out_size > NT * H)
        aux_kernel<<<1, 1>>>(cnt, out, (long)NT * H, 1.0f / (2.0f * NT));
}

// round 5
// speedup vs baseline: 7.9419x; 2.0357x over previous
#include <cuda_runtime.h>
#include <math.h>
#include <stdint.h>

#define H     1024
#define MLPH  4096
#define EXPH  2048
#define NEXP  8
#define NTOK  4096

// tcgen05 is an "a"-suffix feature: real body only in arch-specific passes.
#if !defined(__CUDA_ARCH__) || defined(__CUDA_ARCH_FEAT_SM103_ALL) || defined(__CUDA_ARCH_FEAT_SM100_ALL) || defined(__CUDA_ARCH_SPECIFIC__)
#define TC_OK 1
#else
#define TC_OK 0
#endif

// ---------------- static device scratch ----------------
__device__ float g_xn[(size_t)NTOK * H];
__device__ float g_h1[(size_t)NTOK * MLPH];
__device__ float g_h [(size_t)NTOK * H];
__device__ float g_x2[(size_t)NTOK * H];
__device__ float g_he[(size_t)NEXP * NTOK * EXPH];
__device__ float g_ye[(size_t)NEXP * NTOK * H];
__device__ int   g_cnt[NEXP];
__device__ int   g_tok[NEXP * NTOK];
__device__ int   g_slot[2 * NTOK];
__device__ float g_wgt[2 * NTOK];
// transposed (tf32-rounded) weights: [N, K] K-major
__device__ float g_w1t[(size_t)MLPH * H];
__device__ float g_w2t[(size_t)H * MLPH];
__device__ float g_e1t[(size_t)NEXP * EXPH * H];
__device__ float g_e2t[(size_t)NEXP * H * EXPH];

// ---------------- PTX helpers ----------------
__device__ __forceinline__ uint32_t smem_u32(const void* p) {
    uint32_t a;
    asm("{ .reg .u64 t; cvta.to.shared.u64 t, %1; cvt.u32.u64 %0, t; }" : "=r"(a) : "l"(p));
    return a;
}
__device__ __forceinline__ uint32_t elect_one_pred() {
    uint32_t p;
    asm volatile("{\n\t.reg .pred q;\n\telect.sync _|q, 0xFFFFFFFF;\n\tselp.b32 %0, 1, 0, q;\n\t}" : "=r"(p));
    return p;
}
#define MBARRIER_INIT(addr, cnt) \
    asm volatile("mbarrier.init.shared.b64 [%0], %1;" :: "r"((uint32_t)(addr)), "r"((uint32_t)(cnt)) : "memory")
#define MBARRIER_WAIT_PARITY(addr, par) do { \
    uint32_t _m = (uint32_t)(addr), _p = (uint32_t)(par), _d; \
    asm volatile("{\n\t.reg .pred p;\n\tmbarrier.try_wait.parity.acquire.cta.shared::cta.b64 p, [%1], %2;\n\tselp.b32 %0, 1, 0, p;\n\t}" \
        : "=r"(_d) : "r"(_m), "r"(_p) : "memory"); \
    if (!_d) { \
        asm volatile("{\n\t.reg .pred P1;\n\tWL_%=:\n\tmbarrier.try_wait.parity.acquire.cta.shared::cta.b64 P1, [%0], %1, 0x989680;\n\t@P1 bra.uni WD_%=;\n\tbra.uni WL_%=;\n\tWD_%=:\n\t}" \
            :: "r"(_m), "r"(_p) : "memory"); \
    } } while (0)

__device__ __forceinline__ void cpa16(uint32_t dst, const float* src, uint32_t sz) {
    asm volatile("cp.async.cg.shared.global [%0], [%1], 16, %2;"
        :: "r"(dst), "l"(src), "r"(sz) : "memory");
}
#define CP_COMMIT() asm volatile("cp.async.commit_group;" ::: "memory")
#define CP_WAIT1()  asm volatile("cp.async.wait_group 1;" ::: "memory")
#define CP_WAIT0()  asm volatile("cp.async.wait_group 0;" ::: "memory")

#if TC_OK
#define TCGEN05_ALLOC(saddr, n) \
    asm volatile("tcgen05.alloc.cta_group::1.sync.aligned.shared::cta.b32 [%0], %1;" :: "r"((uint32_t)(saddr)), "r"((uint32_t)(n)) : "memory")
#define TCGEN05_RELINQ() \
    asm volatile("tcgen05.relinquish_alloc_permit.cta_group::1.sync.aligned;")
#define TCGEN05_DEALLOC(taddr, n) \
    asm volatile("tcgen05.dealloc.cta_group::1.sync.aligned.b32 %0, %1;" :: "r"(taddr), "r"((uint32_t)(n)))
#define TCGEN05_COMMIT(mbar) \
    asm volatile("tcgen05.commit.cta_group::1.mbarrier::arrive::one.shared::cluster.b64 [%0];" :: "r"((uint32_t)(mbar)) : "memory")
#define TCGEN05_WAIT_LD()  asm volatile("tcgen05.wait::ld.sync.aligned;" ::: "memory")
#define TCGEN05_FENCE_AFTER()  asm volatile("tcgen05.fence::after_thread_sync;" ::: "memory")
#define TCGEN05_FENCE_BEFORE() asm volatile("tcgen05.fence::before_thread_sync;" ::: "memory")
#define TCGEN05_LD_X32(r, ta) \
    asm volatile("tcgen05.ld.sync.aligned.32x32b.x32.b32 " \
        "{%0, %1, %2, %3, %4, %5, %6, %7, %8, %9, %10, %11, %12, %13, %14, %15, " \
        " %16, %17, %18, %19, %20, %21, %22, %23, %24, %25, %26, %27, %28, %29, %30, %31}, [%32];" \
        : "=r"((r)[0]),  "=r"((r)[1]),  "=r"((r)[2]),  "=r"((r)[3]), \
          "=r"((r)[4]),  "=r"((r)[5]),  "=r"((r)[6]),  "=r"((r)[7]), \
          "=r"((r)[8]),  "=r"((r)[9]),  "=r"((r)[10]), "=r"((r)[11]), \
          "=r"((r)[12]), "=r"((r)[13]), "=r"((r)[14]), "=r"((r)[15]), \
          "=r"((r)[16]), "=r"((r)[17]), "=r"((r)[18]), "=r"((r)[19]), \
          "=r"((r)[20]), "=r"((r)[21]), "=r"((r)[22]), "=r"((r)[23]), \
          "=r"((r)[24]), "=r"((r)[25]), "=r"((r)[26]), "=r"((r)[27]), \
          "=r"((r)[28]), "=r"((r)[29]), "=r"((r)[30]), "=r"((r)[31]) \
        : "r"(ta))

__device__ __forceinline__ void mma_tf32(uint32_t d, uint64_t ad, uint64_t bd, uint32_t idesc, bool acc) {
    uint32_t en = acc ? 1u : 0u, z = 0u;
    asm volatile("{\n\t.reg .pred p;\n\tsetp.ne.u32 p, %5, 0;\n\t"
        "tcgen05.mma.cta_group::1.kind::tf32 [%0], %1, %2, %3, {%4,%4,%4,%4}, p;\n\t}"
        :: "r"(d), "l"(ad), "l"(bd), "r"(idesc), "r"(z), "r"(en) : "memory");
}
#endif // TC_OK

static __device__ __forceinline__ uint64_t make_desc(uint32_t addr) {
    // K-major SW128: layout=2, version=1, SBO=64, LBO=1
    uint64_t d = (uint64_t(2) << 61) | (uint64_t(1) << 46) | (uint64_t(64) << 32) | (uint64_t(1) << 16);
    return d | ((uint64_t)(addr >> 4) & 0x3FFF);
}
__device__ __forceinline__ uint32_t sw128(uint32_t o) { return o ^ ((o >> 3) & 0x70); }
__device__ __forceinline__ float to_tf32(float x) {
    float r; asm("cvt.rna.tf32.f32 %0, %1;" : "=f"(r) : "f"(x)); return r;
}
__device__ __forceinline__ float gelu_exact(float x) {
    return 0.5f * x * (1.0f + erff(x * 0.7071067811865476f));
}

// ---------------- smem map (dynamic, 99328 B) ----------------
// [0:4) tmem ptr  [8:24) mbar[2]
// [1024 + s*16384)  A stage s: 128 rows x 32 k fp32 (SW128)
// [33792 + s*32768) B stage s: 256 rows x 32 k fp32 (SW128)
#define SMEM_BYTES 99328

// ---------------- tcgen05 tf32 GEMM: 128(M) x 256(N), K-stage 32, cp.async feed --
// EPI: 0 = tf32(gelu(acc+bias)), 1 = acc+bias+res, 2 = acc+bias
// B operand is pre-transposed [N, K] K-major, tf32-rounded; ldb = K row stride.
template<int EPI, bool GATHER, bool EXPERT>
__global__ void __launch_bounds__(256, 2)
mma_gemm(const float* __restrict__ A0, int lda, long strideA,
         const float* __restrict__ B0, int ldb, long strideB,
         float* __restrict__ C0, int ldc, long strideC,
         const float* __restrict__ bias0, int strideBias,
         const float* __restrict__ res,
         const int* __restrict__ tok, int tokStride,
         const int* __restrict__ cnt, int M0, int K) {
#if !TC_OK
    return;
#else
    int e = EXPERT ? blockIdx.z : 0;
    int M = EXPERT ? cnt[e] : M0;
    int mBase = blockIdx.y * 128;
    if (mBase >= M) return;
    int colBase = blockIdx.x * 256;

    extern __shared__ char smem[];
    uint32_t sb = smem_u32(smem);
    int tid = threadIdx.x, wid = tid >> 5, lane = tid & 31;

    if (wid == 0) { TCGEN05_ALLOC(sb, 256); TCGEN05_RELINQ(); }
    if (tid == 0) { MBARRIER_INIT(sb + 8, 1); MBARRIER_INIT(sb + 16, 1); }
    __syncthreads();
    uint32_t tmem;
    asm volatile("ld.shared.b32 %0, [%1];" : "=r"(tmem) : "r"(sb));

    const float* A = A0 + ((EXPERT && !GATHER) ? (long)e * strideA : 0);
    const float* B = B0 + (EXPERT ? (long)e * strideB : 0);
    float*       C = C0 + (EXPERT ? (long)e * strideC : 0);
    const float* bias = bias0 + (EXPERT ? e * strideBias : 0);

    // --- A feed: 4 x 16B per thread per stage ---
    const float* aPtr[4]; uint32_t aSz[4]; uint32_t aSoff[4];
    #pragma unroll
    for (int i = 0; i < 4; i++) {
        int idx = tid + 256 * i;
        int r = idx >> 3, kq = idx & 7;
        int grow = mBase + r;
        bool ok = grow < M;
        long rr = ok ? (GATHER ? (long)tok[e * tokStride + grow] : (long)grow) : 0;
        aPtr[i] = A + rr * (long)lda + kq * 4;
        aSz[i] = ok ? 16u : 0u;
        aSoff[i] = sw128((uint32_t)(r * 128 + kq * 16));
    }
    // --- B feed: 8 x 16B per thread per stage (B already [N,K]) ---
    const float* bPtr[8]; uint32_t bSoff[8];
    #pragma unroll
    for (int i = 0; i < 8; i++) {
        int idx = tid + 256 * i;
        int r = idx >> 3, kq = idx & 7;
        bPtr[i] = B + (long)(colBase + r) * ldb + kq * 4;
        bSoff[i] = sw128((uint32_t)(r * 128 + kq * 16));
    }

    const uint32_t aOffBase[2] = { 1024u, 1024u + 16384u };
    const uint32_t bOffBase[2] = { 33792u, 33792u + 32768u };
    uint64_t aDesc[2], bDesc[2];
    #pragma unroll
    for (int s = 0; s < 2; s++) { aDesc[s] = make_desc(sb + aOffBase[s]); bDesc[s] = make_desc(sb + bOffBase[s]); }

    const uint32_t idesc = (1u << 4) | (2u << 7) | (2u << 10) | ((256u / 8) << 17) | ((128u / 16) << 24);

    // stage 0 prefetch
    #pragma unroll
    for (int i = 0; i < 4; i++) cpa16(sb + aOffBase[0] + aSoff[i], aPtr[i], aSz[i]);
    #pragma unroll
    for (int i = 0; i < 8; i++) cpa16(sb + bOffBase[0] + bSoff[i], bPtr[i], 16u);
    CP_COMMIT();

    int T = K / 32;
    int ph0 = 0, ph1 = 0;
    for (int t = 0; t < T; t++) {
        int b = t & 1;
        if (t + 1 < T) {
            int s = b ^ 1;
            if (t >= 1) {
                // MMA(t-1) must release buffer s before we overwrite it
                if (s) { MBARRIER_WAIT_PARITY(sb + 16, ph1); ph1 ^= 1; }
                else   { MBARRIER_WAIT_PARITY(sb + 8,  ph0); ph0 ^= 1; }
            }
            int off = (t + 1) * 32;
            #pragma unroll
            for (int i = 0; i < 4; i++) cpa16(sb + aOffBase[s] + aSoff[i], aPtr[i] + off, aSz[i]);
            #pragma unroll
            for (int i = 0; i < 8; i++) cpa16(sb + bOffBase[s] + bSoff[i], bPtr[i] + off, 16u);
            CP_COMMIT();
            CP_WAIT1();   // stage t landed, stage t+1 still in flight
        } else {
            CP_WAIT0();
        }
        asm volatile("fence.proxy.async.shared::cta;" ::: "memory");
        __syncthreads();
        if (wid == 0 && elect_one_pred()) {
            #pragma unroll
            for (int k = 0; k < 4; k++)
                mma_tf32(tmem, aDesc[b] + k * 2, bDesc[b] + k * 2, idesc, (t > 0) || (k > 0));
            TCGEN05_COMMIT(sb + 8 + b * 8);
        }
    }
    {
        int lb = (T - 1) & 1;
        if (lb) { MBARRIER_WAIT_PARITY(sb + 16, ph1); }
        else    { MBARRIER_WAIT_PARITY(sb + 8,  ph0); }
    }
    TCGEN05_FENCE_AFTER();

    // --- epilogue ---
    int wq = wid & 3, wh = wid >> 2;
    int row = mBase + wq * 32 + lane;
    bool rOk = row < M;
    float* crow = C + (long)row * ldc;
    const float* rrow = res + (long)row * ldc;
    #pragma unroll
    for (int c = 0; c < 4; c++) {
        int col0 = wh * 128 + c * 32;
        uint32_t r[32];
        TCGEN05_LD_X32(r, tmem + col0);
        TCGEN05_WAIT_LD();
        if (rOk) {
            #pragma unroll
            for (int j = 0; j < 32; j += 4) {
                int g = colBase + col0 + j;
                float4 o;
                o.x = __uint_as_float(r[j + 0]) + bias[g + 0];
                o.y = __uint_as_float(r[j + 1]) + bias[g + 1];
                o.z = __uint_as_float(r[j + 2]) + bias[g + 2];
                o.w = __uint_as_float(r[j + 3]) + bias[g + 3];
                if (EPI == 0) {
                    o.x = to_tf32(gelu_exact(o.x)); o.y = to_tf32(gelu_exact(o.y));
                    o.z = to_tf32(gelu_exact(o.z)); o.w = to_tf32(gelu_exact(o.w));
                } else if (EPI == 1) {
                    o.x += rrow[g + 0]; o.y += rrow[g + 1];
                    o.z += rrow[g + 2]; o.w += rrow[g + 3];
                }
                *(float4*)(crow + g) = o;
            }
        }
    }
    TCGEN05_FENCE_BEFORE();
    __syncthreads();
    if (wid == 0) TCGEN05_DEALLOC(tmem, 256);
#endif // TC_OK
}

// ---------------- weight transpose + tf32 pre-round: [R,C] -> [C,R] -------------
__global__ void transpose_tf32(const float* __restrict__ in, float* __restrict__ out,
                               int R, int C) {
    __shared__ float tile[32][33];
    size_t base = (size_t)blockIdx.z * (size_t)R * C;
    in += base; out += base;
    int c0 = blockIdx.x * 32, r0 = blockIdx.y * 32;
    int tx = threadIdx.x, ty = threadIdx.y;
    #pragma unroll
    for (int j = 0; j < 32; j += 8)
        tile[ty + j][tx] = to_tf32(in[(size_t)(r0 + ty + j) * C + c0 + tx]);
    __syncthreads();
    #pragma unroll
    for (int j = 0; j < 32; j += 8)
        out[(size_t)(c0 + ty + j) * R + r0 + tx] = tile[tx][ty + j];
}

// ---------------- block reduce ----------------
__device__ __forceinline__ float block_sum256(float v) {
    __shared__ float s[8];
    __syncthreads();
    #pragma unroll
    for (int o = 16; o; o >>= 1) v += __shfl_down_sync(0xffffffffu, v, o);
    int w = threadIdx.x >> 5, l = threadIdx.x & 31;
    if (l == 0) s[w] = v;
    __syncthreads();
    if (w == 0) {
        float t = (l < 8) ? s[l] : 0.f;
        #pragma unroll
        for (int o = 4; o; o >>= 1) t += __shfl_down_sync(0xffffffffu, t, o);
        if (l == 0) s[0] = t;
    }
    __syncthreads();
    return s[0];
}

// ---------------- LayerNorm (roundOut: emit tf32-rounded for GEMM A feed) -------
__global__ void ln_kernel(const float* __restrict__ in, const float* __restrict__ g,
                          const float* __restrict__ b, float* __restrict__ out,
                          int addSelf, int roundOut) {
    int n = blockIdx.x, tid = threadIdx.x;
    int c = tid * 4;
    float4 xv = *(const float4*)&in[(long)n * H + c];
    float mean = block_sum256(xv.x + xv.y + xv.z + xv.w) * (1.0f / H);
    float dx = xv.x - mean, dy = xv.y - mean, dz = xv.z - mean, dw = xv.w - mean;
    float var = block_sum256(dx*dx + dy*dy + dz*dz + dw*dw) * (1.0f / H);
    float rs = rsqrtf(var + 1e-5f);
    float4 gv = *(const float4*)&g[c];
    float4 bv = *(const float4*)&b[c];
    float4 o;
    o.x = dx * rs * gv.x + bv.x;
    o.y = dy * rs * gv.y + bv.y;
    o.z = dz * rs * gv.z + bv.z;
    o.w = dw * rs * gv.w + bv.w;
    if (addSelf) { o.x += xv.x; o.y += xv.y; o.z += xv.z; o.w += xv.w; }
    if (roundOut) {
        o.x = to_tf32(o.x); o.y = to_tf32(o.y);
        o.z = to_tf32(o.z); o.w = to_tf32(o.w);
    }
    *(float4*)&out[(long)n * H + c] = o;
}

// ---------------- router ----------------
__global__ void router_kernel(const float* __restrict__ x2, const float* __restrict__ rw,
                              int* __restrict__ cnt, int* __restrict__ tok,
                              int* __restrict__ slot, float* __restrict__ wgt, int NT) {
    int warp = threadIdx.x >> 5, lane = threadIdx.x & 31;
    int n = blockIdx.x * 4 + warp;
    if (n >= NT) return;
    float acc[NEXP];
    #pragma unroll
    for (int e = 0; e < NEXP; e++) acc[e] = 0.f;
    const float* xr = x2 + (long)n * H;
    for (int h = lane; h < H; h += 32) {
        float xv = xr[h];
        const float4* r = (const float4*)&rw[h * NEXP];
        float4 r0 = r[0], r1 = r[1];
        acc[0] += xv * r0.x; acc[1] += xv * r0.y; acc[2] += xv * r0.z; acc[3] += xv * r0.w;
        acc[4] += xv * r1.x; acc[5] += xv * r1.y; acc[6] += xv * r1.z; acc[7] += xv * r1.w;
    }
    #pragma unroll
    for (int e = 0; e < NEXP; e++)
        #pragma unroll
        for (int o = 16; o; o >>= 1) acc[e] += __shfl_down_sync(0xffffffffu, acc[e], o);
    if (lane == 0) {
        int i1 = 0;
        #pragma unroll
        for (int e = 1; e < NEXP; e++) if (acc[e] > acc[i1]) i1 = e;
        int i2 = (i1 == 0) ? 1 : 0;
        #pragma unroll
        for (int e = 0; e < NEXP; e++) { if (e == i1 || e == i2) continue; if (acc[e] > acc[i2]) i2 = e; }
        float d  = expf(acc[i2] - acc[i1]);
        float w1 = 1.0f / (1.0f + d);
        float w2 = d / (1.0f + d);
        int p1 = atomicAdd(&cnt[i1], 1);
        int p2 = atomicAdd(&cnt[i2], 1);
        tok[i1 * NT + p1] = n;
        tok[i2 * NT + p2] = n;
        slot[2*n]   = i1 * NT + p1;  wgt[2*n]   = w1;
        slot[2*n+1] = i2 * NT + p2;  wgt[2*n+1] = w2;
    }
}

// ---------------- combine + final LN ----------------
__global__ void combine_ln_kernel(const float* __restrict__ ye, const int* __restrict__ slot,
                                  const float* __restrict__ wgt, const float* __restrict__ g,
                                  const float* __restrict__ b, float* __restrict__ out) {
    int n = blockIdx.x, tid = threadIdx.x;
    int s0 = slot[2*n], s1 = slot[2*n+1];
    float w0 = wgt[2*n], w1 = wgt[2*n+1];
    int c = tid * 4;
    float4 y0 = *(const float4*)&ye[(long)s0 * H + c];
    float4 y1 = *(const float4*)&ye[(long)s1 * H + c];
    float4 v;
    v.x = w0*y0.x + w1*y1.x; v.y = w0*y0.y + w1*y1.y;
    v.z = w0*y0.z + w1*y1.z; v.w = w0*y0.w + w1*y1.w;
    float mean = block_sum256(v.x + v.y + v.z + v.w) * (1.0f / H);
    float dx = v.x - mean, dy = v.y - mean, dz = v.z - mean, dw = v.w - mean;
    float var = block_sum256(dx*dx + dy*dy + dz*dz + dw*dw) * (1.0f / H);
    float rs = rsqrtf(var + 1e-5f);
    float4 gv = *(const float4*)&g[c];
    float4 bv = *(const float4*)&b[c];
    float4 o;
    o.x = dx * rs * gv.x + bv.x;
    o.y = dy * rs * gv.y + bv.y;
    o.z = dz * rs * gv.z + bv.z;
    o.w = dw * rs * gv.w + bv.w;
    *(float4*)&out[(long)n * H + c] = o;
}

__global__ void aux_kernel(const int* __restrict__ cnt, float* __restrict__ out,
                           long auxIdx, float invTotal) {
    float a = 0.f;
    #pragma unroll
    for (int e = 0; e < NEXP; e++) {
        float load = (float)cnt[e] * invTotal;
        a += load * logf(load + 1e-9f);
    }
    out[auxIdx] = 0.01f * a;
}

__global__ void reset_kernel(int* cnt) { if (threadIdx.x < NEXP) cnt[threadIdx.x] = 0; }

// ---------------- launch ----------------
extern "C" void kernel_launch(void* const* d_in, const int* in_sizes, int n_in,
                              void* d_out, int out_size) {
    const float* x    = (const float*)d_in[0];
    const float* ln1g = (const float*)d_in[1];
    const float* ln1b = (const float*)d_in[2];
    const float* ln2g = (const float*)d_in[3];
    const float* ln2b = (const float*)d_in[4];
    const float* w1   = (const float*)d_in[5];
    const float* b1   = (const float*)d_in[6];
    const float* w2   = (const float*)d_in[7];
    const float* b2   = (const float*)d_in[8];
    const float* rw   = (const float*)d_in[9];
    const float* ew1  = (const float*)d_in[10];
    const float* eb1  = (const float*)d_in[11];
    const float* ew2  = (const float*)d_in[12];
    const float* eb2  = (const float*)d_in[13];
    const float* lnfg = (const float*)d_in[14];
    const float* lnfb = (const float*)d_in[15];
    float* out = (float*)d_out;

    int NT = in_sizes[0] / H;   // 4096

    float *xn, *h1, *hh, *x2, *he, *ye, *wgt, *w1t, *w2t, *e1t, *e2t;
    int *cnt, *tok, *slot;
    cudaGetSymbolAddress((void**)&xn,   g_xn);
    cudaGetSymbolAddress((void**)&h1,   g_h1);
    cudaGetSymbolAddress((void**)&hh,   g_h);
    cudaGetSymbolAddress((void**)&x2,   g_x2);
    cudaGetSymbolAddress((void**)&he,   g_he);
    cudaGetSymbolAddress((void**)&ye,   g_ye);
    cudaGetSymbolAddress((void**)&wgt,  g_wgt);
    cudaGetSymbolAddress((void**)&cnt,  g_cnt);
    cudaGetSymbolAddress((void**)&tok,  g_tok);
    cudaGetSymbolAddress((void**)&slot, g_slot);
    cudaGetSymbolAddress((void**)&w1t,  g_w1t);
    cudaGetSymbolAddress((void**)&w2t,  g_w2t);
    cudaGetSymbolAddress((void**)&e1t,  g_e1t);
    cudaGetSymbolAddress((void**)&e2t,  g_e2t);

    cudaFuncSetAttribute(mma_gemm<0, false, false>, cudaFuncAttributeMaxDynamicSharedMemorySize, SMEM_BYTES);
    cudaFuncSetAttribute(mma_gemm<1, false, false>, cudaFuncAttributeMaxDynamicSharedMemorySize, SMEM_BYTES);
    cudaFuncSetAttribute(mma_gemm<0, true,  true >, cudaFuncAttributeMaxDynamicSharedMemorySize, SMEM_BYTES);
    cudaFuncSetAttribute(mma_gemm<2, false, true >, cudaFuncAttributeMaxDynamicSharedMemorySize, SMEM_BYTES);

    reset_kernel<<<1, 32>>>(cnt);

    // weight transpose + tf32 pre-round (in-graph, ~50us)
    dim3 tb(32, 8);
    transpose_tf32<<<dim3(MLPH/32, H/32, 1),    tb>>>(w1,  w1t, H,    MLPH);
    transpose_tf32<<<dim3(H/32,    MLPH/32, 1), tb>>>(w2,  w2t, MLPH, H);
    transpose_tf32<<<dim3(EXPH/32, H/32, NEXP), tb>>>(ew1, e1t, H,    EXPH);
    transpose_tf32<<<dim3(H/32, EXPH/32, NEXP), tb>>>(ew2, e2t, EXPH, H);

    // ResMLP block
    ln_kernel<<<NT, 256>>>(x, ln1g, ln1b, xn, 0, 1);
    mma_gemm<0, false, false><<<dim3(MLPH/256, NT/128), 256, SMEM_BYTES>>>(
        xn, H, 0,  w1t, H, 0,  h1, MLPH, 0,  b1, 0,
        nullptr, nullptr, 0, nullptr, NT, H);
    mma_gemm<1, false, false><<<dim3(H/256, NT/128), 256, SMEM_BYTES>>>(
        h1, MLPH, 0,  w2t, MLPH, 0,  hh, H, 0,  b2, 0,
        x, nullptr, 0, nullptr, NT, MLPH);
    ln_kernel<<<NT, 256>>>(hh, ln2g, ln2b, x2, 1, 1);

    // MoE
    router_kernel<<<(NT + 3) / 4, 128>>>(x2, rw, cnt, tok, slot, wgt, NT);
    mma_gemm<0, true, true><<<dim3(EXPH/256, NT/128, NEXP), 256, SMEM_BYTES>>>(
        x2, H, 0,  e1t, H, (long)EXPH * H,  he, EXPH, (long)NT * EXPH,
        eb1, EXPH, nullptr, tok, NT, cnt, NT, H);
    mma_gemm<2, false, true><<<dim3(H/256, NT/128, NEXP), 256, SMEM_BYTES>>>(
        he, EXPH, (long)NT * EXPH,  e2t, EXPH, (long)H * EXPH,  ye, H, (long)NT * H,
        eb2, H, nullptr, nullptr, 0, cnt, NT, EXPH);

    // combine + final LN + aux
    combine_ln_kernel<<<NT, 256>>>(ye, slot, wgt, lnfg, lnfb, out);
    if (out_size > NT * H)
        aux_kernel<<<1, 1>>>(cnt, out, (long)NT * H, 1.0f / (2.0f * NT));
}

// round 6
// speedup vs baseline: 10.0287x; 1.2628x over previous
#include <cuda_runtime.h>
#include <cuda_fp16.h>
#include <math.h>
#include <stdint.h>

#define H     1024
#define MLPH  4096
#define EXPH  2048
#define NEXP  8
#define NTOK  4096

// tcgen05 is an "a"-suffix feature: real body only in arch-specific passes.
#if !defined(__CUDA_ARCH__) || defined(__CUDA_ARCH_FEAT_SM103_ALL) || defined(__CUDA_ARCH_FEAT_SM100_ALL) || defined(__CUDA_ARCH_SPECIFIC__)
#define TC_OK 1
#else
#define TC_OK 0
#endif

// ---------------- static device scratch ----------------
__device__ __half g_xn [(size_t)NTOK * H];            // LN1(x) fp16
__device__ __half g_h1 [(size_t)NTOK * MLPH];         // gelu(xn@w1+b1) fp16
__device__ float  g_h  [(size_t)NTOK * H];            // h1@w2+b2+x fp32
__device__ __half g_x2h[(size_t)NTOK * H];            // LN2(h)+h fp16 (GEMM feed)
__device__ float  g_x2f[(size_t)NTOK * H];            // LN2(h)+h fp32 (router feed)
__device__ __half g_he [(size_t)NEXP * NTOK * EXPH];  // expert hidden fp16
__device__ float  g_ye [(size_t)NEXP * NTOK * H];     // expert out fp32
__device__ int    g_cnt[NEXP];
__device__ int    g_tok[NEXP * NTOK];
__device__ int    g_slot[2 * NTOK];
__device__ float  g_wgt[2 * NTOK];
// transposed fp16 weights: [N, K] K-major
__device__ __half g_w1t[(size_t)MLPH * H];
__device__ __half g_w2t[(size_t)H * MLPH];
__device__ __half g_e1t[(size_t)NEXP * EXPH * H];
__device__ __half g_e2t[(size_t)NEXP * H * EXPH];

// ---------------- PTX helpers ----------------
__device__ __forceinline__ uint32_t smem_u32(const void* p) {
    uint32_t a;
    asm("{ .reg .u64 t; cvta.to.shared.u64 t, %1; cvt.u32.u64 %0, t; }" : "=r"(a) : "l"(p));
    return a;
}
__device__ __forceinline__ uint32_t elect_one_pred() {
    uint32_t p;
    asm volatile("{\n\t.reg .pred q;\n\telect.sync _|q, 0xFFFFFFFF;\n\tselp.b32 %0, 1, 0, q;\n\t}" : "=r"(p));
    return p;
}
#define MBARRIER_INIT(addr, cnt) \
    asm volatile("mbarrier.init.shared.b64 [%0], %1;" :: "r"((uint32_t)(addr)), "r"((uint32_t)(cnt)) : "memory")
#define MBARRIER_WAIT_PARITY(addr, par) do { \
    uint32_t _m = (uint32_t)(addr), _p = (uint32_t)(par), _d; \
    asm volatile("{\n\t.reg .pred p;\n\tmbarrier.try_wait.parity.acquire.cta.shared::cta.b64 p, [%1], %2;\n\tselp.b32 %0, 1, 0, p;\n\t}" \
        : "=r"(_d) : "r"(_m), "r"(_p) : "memory"); \
    if (!_d) { \
        asm volatile("{\n\t.reg .pred P1;\n\tWL_%=:\n\tmbarrier.try_wait.parity.acquire.cta.shared::cta.b64 P1, [%0], %1, 0x989680;\n\t@P1 bra.uni WD_%=;\n\tbra.uni WL_%=;\n\tWD_%=:\n\t}" \
            :: "r"(_m), "r"(_p) : "memory"); \
    } } while (0)

__device__ __forceinline__ void cpa16(uint32_t dst, const void* src, uint32_t sz) {
    asm volatile("cp.async.cg.shared.global [%0], [%1], 16, %2;"
        :: "r"(dst), "l"(src), "r"(sz) : "memory");
}
#define CP_COMMIT() asm volatile("cp.async.commit_group;" ::: "memory")
#define CP_WAIT1()  asm volatile("cp.async.wait_group 1;" ::: "memory")
#define CP_WAIT0()  asm volatile("cp.async.wait_group 0;" ::: "memory")

#if TC_OK
#define TCGEN05_ALLOC(saddr, n) \
    asm volatile("tcgen05.alloc.cta_group::1.sync.aligned.shared::cta.b32 [%0], %1;" :: "r"((uint32_t)(saddr)), "r"((uint32_t)(n)) : "memory")
#define TCGEN05_RELINQ() \
    asm volatile("tcgen05.relinquish_alloc_permit.cta_group::1.sync.aligned;")
#define TCGEN05_DEALLOC(taddr, n) \
    asm volatile("tcgen05.dealloc.cta_group::1.sync.aligned.b32 %0, %1;" :: "r"(taddr), "r"((uint32_t)(n)))
#define TCGEN05_COMMIT(mbar) \
    asm volatile("tcgen05.commit.cta_group::1.mbarrier::arrive::one.shared::cluster.b64 [%0];" :: "r"((uint32_t)(mbar)) : "memory")
#define TCGEN05_WAIT_LD()  asm volatile("tcgen05.wait::ld.sync.aligned;" ::: "memory")
#define TCGEN05_FENCE_AFTER()  asm volatile("tcgen05.fence::after_thread_sync;" ::: "memory")
#define TCGEN05_FENCE_BEFORE() asm volatile("tcgen05.fence::before_thread_sync;" ::: "memory")
#define TCGEN05_LD_X32(r, ta) \
    asm volatile("tcgen05.ld.sync.aligned.32x32b.x32.b32 " \
        "{%0, %1, %2, %3, %4, %5, %6, %7, %8, %9, %10, %11, %12, %13, %14, %15, " \
        " %16, %17, %18, %19, %20, %21, %22, %23, %24, %25, %26, %27, %28, %29, %30, %31}, [%32];" \
        : "=r"((r)[0]),  "=r"((r)[1]),  "=r"((r)[2]),  "=r"((r)[3]), \
          "=r"((r)[4]),  "=r"((r)[5]),  "=r"((r)[6]),  "=r"((r)[7]), \
          "=r"((r)[8]),  "=r"((r)[9]),  "=r"((r)[10]), "=r"((r)[11]), \
          "=r"((r)[12]), "=r"((r)[13]), "=r"((r)[14]), "=r"((r)[15]), \
          "=r"((r)[16]), "=r"((r)[17]), "=r"((r)[18]), "=r"((r)[19]), \
          "=r"((r)[20]), "=r"((r)[21]), "=r"((r)[22]), "=r"((r)[23]), \
          "=r"((r)[24]), "=r"((r)[25]), "=r"((r)[26]), "=r"((r)[27]), \
          "=r"((r)[28]), "=r"((r)[29]), "=r"((r)[30]), "=r"((r)[31]) \
        : "r"(ta))

__device__ __forceinline__ void mma_f16(uint32_t d, uint64_t ad, uint64_t bd, uint32_t idesc, bool acc) {
    uint32_t en = acc ? 1u : 0u, z = 0u;
    asm volatile("{\n\t.reg .pred p;\n\tsetp.ne.u32 p, %5, 0;\n\t"
        "tcgen05.mma.cta_group::1.kind::f16 [%0], %1, %2, %3, {%4,%4,%4,%4}, p;\n\t}"
        :: "r"(d), "l"(ad), "l"(bd), "r"(idesc), "r"(z), "r"(en) : "memory");
}
#endif // TC_OK

static __device__ __forceinline__ uint64_t make_desc(uint32_t addr) {
    // K-major SW128: layout=2, version=1, SBO=64, LBO=1
    uint64_t d = (uint64_t(2) << 61) | (uint64_t(1) << 46) | (uint64_t(64) << 32) | (uint64_t(1) << 16);
    return d | ((uint64_t)(addr >> 4) & 0x3FFF);
}
__device__ __forceinline__ uint32_t sw128(uint32_t o) { return o ^ ((o >> 3) & 0x70); }
__device__ __forceinline__ float gelu_exact(float x) {
    return 0.5f * x * (1.0f + erff(x * 0.7071067811865476f));
}

template<bool B> struct OutSel;
template<> struct OutSel<true>  { using T = __half; };
template<> struct OutSel<false> { using T = float;  };

// ---------------- smem map (dynamic, 99328 B) ----------------
// [0:4) tmem ptr  [8:24) mbar[2]
// [1024 + s*16384)  A stage s: 128 rows x 64 k fp16 (SW128, 128 B/row)
// [33792 + s*32768) B stage s: 256 rows x 64 k fp16 (SW128, 128 B/row)
#define SMEM_BYTES 99328

// ------ tcgen05 fp16 GEMM: 128(M) x 256(N), K-stage 64, cp.async feed ------
// EPI: 0 = half(gelu(acc+bias)), 1 = acc+bias+res (float), 2 = acc+bias (float)
// A, B fp16; B pre-transposed [N, K] K-major. lda/ldb/ldc in elements.
template<int EPI, bool GATHER, bool EXPERT>
__global__ void __launch_bounds__(256, 2)
mma_gemm(const __half* __restrict__ A0, int lda, long strideA,
         const __half* __restrict__ B0, int ldb, long strideB,
         void* __restrict__ C0v, int ldc, long strideC,
         const float* __restrict__ bias0, int strideBias,
         const float* __restrict__ res,
         const int* __restrict__ tok, int tokStride,
         const int* __restrict__ cnt, int M0, int K) {
#if !TC_OK
    return;
#else
    using CT = typename OutSel<EPI == 0>::T;
    CT* C0 = (CT*)C0v;

    int e = EXPERT ? blockIdx.z : 0;
    int M = EXPERT ? cnt[e] : M0;
    int mBase = blockIdx.y * 128;
    if (mBase >= M) return;
    int colBase = blockIdx.x * 256;

    extern __shared__ char smem[];
    uint32_t sb = smem_u32(smem);
    int tid = threadIdx.x, wid = tid >> 5, lane = tid & 31;

    if (wid == 0) { TCGEN05_ALLOC(sb, 256); TCGEN05_RELINQ(); }
    if (tid == 0) { MBARRIER_INIT(sb + 8, 1); MBARRIER_INIT(sb + 16, 1); }
    __syncthreads();
    uint32_t tmem;
    asm volatile("ld.shared.b32 %0, [%1];" : "=r"(tmem) : "r"(sb));

    const __half* A = A0 + ((EXPERT && !GATHER) ? (long)e * strideA : 0);
    const __half* B = B0 + (EXPERT ? (long)e * strideB : 0);
    CT*           C = C0 + (EXPERT ? (long)e * strideC : 0);
    const float* bias = bias0 + (EXPERT ? e * strideBias : 0);

    // --- A feed: 4 x 16B per thread per stage (128 rows x 128 B) ---
    const __half* aPtr[4]; uint32_t aSz[4]; uint32_t aSoff[4];
    #pragma unroll
    for (int i = 0; i < 4; i++) {
        int idx = tid + 256 * i;
        int r = idx >> 3, kq = idx & 7;   // kq: 16B chunk = 8 fp16
        int grow = mBase + r;
        bool ok = grow < M;
        long rr = ok ? (GATHER ? (long)tok[e * tokStride + grow] : (long)grow) : 0;
        aPtr[i] = A + rr * (long)lda + kq * 8;
        aSz[i] = ok ? 16u : 0u;
        aSoff[i] = sw128((uint32_t)(r * 128 + kq * 16));
    }
    // --- B feed: 8 x 16B per thread per stage (256 rows x 128 B) ---
    const __half* bPtr[8]; uint32_t bSoff[8];
    #pragma unroll
    for (int i = 0; i < 8; i++) {
        int idx = tid + 256 * i;
        int r = idx >> 3, kq = idx & 7;
        bPtr[i] = B + (long)(colBase + r) * ldb + kq * 8;
        bSoff[i] = sw128((uint32_t)(r * 128 + kq * 16));
    }

    const uint32_t aOffBase[2] = { 1024u, 1024u + 16384u };
    const uint32_t bOffBase[2] = { 33792u, 33792u + 32768u };
    uint64_t aDesc[2], bDesc[2];
    #pragma unroll
    for (int s = 0; s < 2; s++) { aDesc[s] = make_desc(sb + aOffBase[s]); bDesc[s] = make_desc(sb + bOffBase[s]); }

    // idesc kind::f16: dtype F32=1 [4:5], atype FP16=0 [7:9], btype FP16=0 [10:12],
    //                  N/8 [17:22], M/16 [24:28]
    const uint32_t idesc = (1u << 4) | ((256u / 8) << 17) | ((128u / 16) << 24);

    // stage 0 prefetch
    #pragma unroll
    for (int i = 0; i < 4; i++) cpa16(sb + aOffBase[0] + aSoff[i], aPtr[i], aSz[i]);
    #pragma unroll
    for (int i = 0; i < 8; i++) cpa16(sb + bOffBase[0] + bSoff[i], bPtr[i], 16u);
    CP_COMMIT();

    int T = K / 64;
    int ph0 = 0, ph1 = 0;
    for (int t = 0; t < T; t++) {
        int b = t & 1;
        if (t + 1 < T) {
            int s = b ^ 1;
            if (t >= 1) {
                if (s) { MBARRIER_WAIT_PARITY(sb + 16, ph1); ph1 ^= 1; }
                else   { MBARRIER_WAIT_PARITY(sb + 8,  ph0); ph0 ^= 1; }
            }
            int off = (t + 1) * 64;     // fp16 elements
            #pragma unroll
            for (int i = 0; i < 4; i++) cpa16(sb + aOffBase[s] + aSoff[i], aPtr[i] + off, aSz[i]);
            #pragma unroll
            for (int i = 0; i < 8; i++) cpa16(sb + bOffBase[s] + bSoff[i], bPtr[i] + off, 16u);
            CP_COMMIT();
            CP_WAIT1();
        } else {
            CP_WAIT0();
        }
        asm volatile("fence.proxy.async.shared::cta;" ::: "memory");
        __syncthreads();
        if (wid == 0 && elect_one_pred()) {
            // 4 dispatches cover K=64 (16 per dispatch); desc step = 32 B = 2 units
            #pragma unroll
            for (int k = 0; k < 4; k++)
                mma_f16(tmem, aDesc[b] + k * 2, bDesc[b] + k * 2, idesc, (t > 0) || (k > 0));
            TCGEN05_COMMIT(sb + 8 + b * 8);
        }
    }
    {
        int lb = (T - 1) & 1;
        if (lb) { MBARRIER_WAIT_PARITY(sb + 16, ph1); }
        else    { MBARRIER_WAIT_PARITY(sb + 8,  ph0); }
    }
    TCGEN05_FENCE_AFTER();

    // --- epilogue ---
    int wq = wid & 3, wh = wid >> 2;
    int row = mBase + wq * 32 + lane;
    bool rOk = row < M;
    CT* crow = C + (long)row * ldc;
    const float* rrow = res + (long)row * ldc;
    #pragma unroll
    for (int c = 0; c < 4; c++) {
        int col0 = wh * 128 + c * 32;
        uint32_t r[32];
        TCGEN05_LD_X32(r, tmem + col0);
        TCGEN05_WAIT_LD();
        if (rOk) {
            #pragma unroll
            for (int j = 0; j < 32; j += 4) {
                int g = colBase + col0 + j;
                float4 o;
                o.x = __uint_as_float(r[j + 0]) + bias[g + 0];
                o.y = __uint_as_float(r[j + 1]) + bias[g + 1];
                o.z = __uint_as_float(r[j + 2]) + bias[g + 2];
                o.w = __uint_as_float(r[j + 3]) + bias[g + 3];
                if (EPI == 0) {
                    __half2 h0 = __floats2half2_rn(gelu_exact(o.x), gelu_exact(o.y));
                    __half2 h1v = __floats2half2_rn(gelu_exact(o.z), gelu_exact(o.w));
                    __half2* hp = (__half2*)((__half*)crow + g);
                    hp[0] = h0; hp[1] = h1v;
                } else {
                    if (EPI == 1) {
                        o.x += rrow[g + 0]; o.y += rrow[g + 1];
                        o.z += rrow[g + 2]; o.w += rrow[g + 3];
                    }
                    *(float4*)((float*)crow + g) = o;
                }
            }
        }
    }
    TCGEN05_FENCE_BEFORE();
    __syncthreads();
    if (wid == 0) TCGEN05_DEALLOC(tmem, 256);
#endif // TC_OK
}

// ---------------- weight transpose fp32 [R,C] -> fp16 [C,R] ----------------
__global__ void transpose_h(const float* __restrict__ in, __half* __restrict__ out,
                            int R, int C) {
    __shared__ float tile[32][33];
    in  += (size_t)blockIdx.z * (size_t)R * C;
    out += (size_t)blockIdx.z * (size_t)R * C;
    int c0 = blockIdx.x * 32, r0 = blockIdx.y * 32;
    int tx = threadIdx.x, ty = threadIdx.y;
    #pragma unroll
    for (int j = 0; j < 32; j += 8)
        tile[ty + j][tx] = in[(size_t)(r0 + ty + j) * C + c0 + tx];
    __syncthreads();
    #pragma unroll
    for (int j = 0; j < 32; j += 8)
        out[(size_t)(c0 + ty + j) * R + r0 + tx] = __float2half_rn(tile[tx][ty + j]);
}

// ---------------- block reduce ----------------
__device__ __forceinline__ float block_sum256(float v) {
    __shared__ float s[8];
    __syncthreads();
    #pragma unroll
    for (int o = 16; o; o >>= 1) v += __shfl_down_sync(0xffffffffu, v, o);
    int w = threadIdx.x >> 5, l = threadIdx.x & 31;
    if (l == 0) s[w] = v;
    __syncthreads();
    if (w == 0) {
        float t = (l < 8) ? s[l] : 0.f;
        #pragma unroll
        for (int o = 4; o; o >>= 1) t += __shfl_down_sync(0xffffffffu, t, o);
        if (l == 0) s[0] = t;
    }
    __syncthreads();
    return s[0];
}

// ---------------- LayerNorm: fp16 out (GEMM feed) + optional fp32 copy ---------
__global__ void ln_kernel(const float* __restrict__ in, const float* __restrict__ g,
                          const float* __restrict__ b, __half* __restrict__ outH,
                          float* __restrict__ outF, int addSelf) {
    int n = blockIdx.x, tid = threadIdx.x;
    int c = tid * 4;
    float4 xv = *(const float4*)&in[(long)n * H + c];
    float mean = block_sum256(xv.x + xv.y + xv.z + xv.w) * (1.0f / H);
    float dx = xv.x - mean, dy = xv.y - mean, dz = xv.z - mean, dw = xv.w - mean;
    float var = block_sum256(dx*dx + dy*dy + dz*dz + dw*dw) * (1.0f / H);
    float rs = rsqrtf(var + 1e-5f);
    float4 gv = *(const float4*)&g[c];
    float4 bv = *(const float4*)&b[c];
    float4 o;
    o.x = dx * rs * gv.x + bv.x;
    o.y = dy * rs * gv.y + bv.y;
    o.z = dz * rs * gv.z + bv.z;
    o.w = dw * rs * gv.w + bv.w;
    if (addSelf) { o.x += xv.x; o.y += xv.y; o.z += xv.z; o.w += xv.w; }
    __half2* hp = (__half2*)&outH[(long)n * H + c];
    hp[0] = __floats2half2_rn(o.x, o.y);
    hp[1] = __floats2half2_rn(o.z, o.w);
    if (outF) *(float4*)&outF[(long)n * H + c] = o;
}

// ---------------- router (fp32 logits -> exact top-2 selection) ----------------
__global__ void router_kernel(const float* __restrict__ x2, const float* __restrict__ rw,
                              int* __restrict__ cnt, int* __restrict__ tok,
                              int* __restrict__ slot, float* __restrict__ wgt, int NT) {
    int warp = threadIdx.x >> 5, lane = threadIdx.x & 31;
    int n = blockIdx.x * 4 + warp;
    if (n >= NT) return;
    float acc[NEXP];
    #pragma unroll
    for (int e = 0; e < NEXP; e++) acc[e] = 0.f;
    const float* xr = x2 + (long)n * H;
    for (int h = lane; h < H; h += 32) {
        float xv = xr[h];
        const float4* r = (const float4*)&rw[h * NEXP];
        float4 r0 = r[0], r1 = r[1];
        acc[0] += xv * r0.x; acc[1] += xv * r0.y; acc[2] += xv * r0.z; acc[3] += xv * r0.w;
        acc[4] += xv * r1.x; acc[5] += xv * r1.y; acc[6] += xv * r1.z; acc[7] += xv * r1.w;
    }
    #pragma unroll
    for (int e = 0; e < NEXP; e++)
        #pragma unroll
        for (int o = 16; o; o >>= 1) acc[e] += __shfl_down_sync(0xffffffffu, acc[e], o);
    if (lane == 0) {
        int i1 = 0;
        #pragma unroll
        for (int e = 1; e < NEXP; e++) if (acc[e] > acc[i1]) i1 = e;
        int i2 = (i1 == 0) ? 1 : 0;
        #pragma unroll
        for (int e = 0; e < NEXP; e++) { if (e == i1 || e == i2) continue; if (acc[e] > acc[i2]) i2 = e; }
        float d  = expf(acc[i2] - acc[i1]);
        float w1 = 1.0f / (1.0f + d);
        float w2 = d / (1.0f + d);
        int p1 = atomicAdd(&cnt[i1], 1);
        int p2 = atomicAdd(&cnt[i2], 1);
        tok[i1 * NT + p1] = n;
        tok[i2 * NT + p2] = n;
        slot[2*n]   = i1 * NT + p1;  wgt[2*n]   = w1;
        slot[2*n+1] = i2 * NT + p2;  wgt[2*n+1] = w2;
    }
}

// ---------------- combine + final LN ----------------
__global__ void combine_ln_kernel(const float* __restrict__ ye, const int* __restrict__ slot,
                                  const float* __restrict__ wgt, const float* __restrict__ g,
                                  const float* __restrict__ b, float* __restrict__ out) {
    int n = blockIdx.x, tid = threadIdx.x;
    int s0 = slot[2*n], s1 = slot[2*n+1];
    float w0 = wgt[2*n], w1 = wgt[2*n+1];
    int c = tid * 4;
    float4 y0 = *(const float4*)&ye[(long)s0 * H + c];
    float4 y1 = *(const float4*)&ye[(long)s1 * H + c];
    float4 v;
    v.x = w0*y0.x + w1*y1.x; v.y = w0*y0.y + w1*y1.y;
    v.z = w0*y0.z + w1*y1.z; v.w = w0*y0.w + w1*y1.w;
    float mean = block_sum256(v.x + v.y + v.z + v.w) * (1.0f / H);
    float dx = v.x - mean, dy = v.y - mean, dz = v.z - mean, dw = v.w - mean;
    float var = block_sum256(dx*dx + dy*dy + dz*dz + dw*dw) * (1.0f / H);
    float rs = rsqrtf(var + 1e-5f);
    float4 gv = *(const float4*)&g[c];
    float4 bv = *(const float4*)&b[c];
    float4 o;
    o.x = dx * rs * gv.x + bv.x;
    o.y = dy * rs * gv.y + bv.y;
    o.z = dz * rs * gv.z + bv.z;
    o.w = dw * rs * gv.w + bv.w;
    *(float4*)&out[(long)n * H + c] = o;
}

__global__ void aux_kernel(const int* __restrict__ cnt, float* __restrict__ out,
                           long auxIdx, float invTotal) {
    float a = 0.f;
    #pragma unroll
    for (int e = 0; e < NEXP; e++) {
        float load = (float)cnt[e] * invTotal;
        a += load * logf(load + 1e-9f);
    }
    out[auxIdx] = 0.01f * a;
}

__global__ void reset_kernel(int* cnt) { if (threadIdx.x < NEXP) cnt[threadIdx.x] = 0; }

// ---------------- launch ----------------
extern "C" void kernel_launch(void* const* d_in, const int* in_sizes, int n_in,
                              void* d_out, int out_size) {
    const float* x    = (const float*)d_in[0];
    const float* ln1g = (const float*)d_in[1];
    const float* ln1b = (const float*)d_in[2];
    const float* ln2g = (const float*)d_in[3];
    const float* ln2b = (const float*)d_in[4];
    const float* w1   = (const float*)d_in[5];
    const float* b1   = (const float*)d_in[6];
    const float* w2   = (const float*)d_in[7];
    const float* b2   = (const float*)d_in[8];
    const float* rw   = (const float*)d_in[9];
    const float* ew1  = (const float*)d_in[10];
    const float* eb1  = (const float*)d_in[11];
    const float* ew2  = (const float*)d_in[12];
    const float* eb2  = (const float*)d_in[13];
    const float* lnfg = (const float*)d_in[14];
    const float* lnfb = (const float*)d_in[15];
    float* out = (float*)d_out;

    int NT = in_sizes[0] / H;   // 4096

    __half *xn, *h1, *x2h, *he, *w1t, *w2t, *e1t, *e2t;
    float *hh, *x2f, *ye, *wgt;
    int *cnt, *tok, *slot;
    cudaGetSymbolAddress((void**)&xn,   g_xn);
    cudaGetSymbolAddress((void**)&h1,   g_h1);
    cudaGetSymbolAddress((void**)&hh,   g_h);
    cudaGetSymbolAddress((void**)&x2h,  g_x2h);
    cudaGetSymbolAddress((void**)&x2f,  g_x2f);
    cudaGetSymbolAddress((void**)&he,   g_he);
    cudaGetSymbolAddress((void**)&ye,   g_ye);
    cudaGetSymbolAddress((void**)&wgt,  g_wgt);
    cudaGetSymbolAddress((void**)&cnt,  g_cnt);
    cudaGetSymbolAddress((void**)&tok,  g_tok);
    cudaGetSymbolAddress((void**)&slot, g_slot);
    cudaGetSymbolAddress((void**)&w1t,  g_w1t);
    cudaGetSymbolAddress((void**)&w2t,  g_w2t);
    cudaGetSymbolAddress((void**)&e1t,  g_e1t);
    cudaGetSymbolAddress((void**)&e2t,  g_e2t);

    cudaFuncSetAttribute(mma_gemm<0, false, false>, cudaFuncAttributeMaxDynamicSharedMemorySize, SMEM_BYTES);
    cudaFuncSetAttribute(mma_gemm<1, false, false>, cudaFuncAttributeMaxDynamicSharedMemorySize, SMEM_BYTES);
    cudaFuncSetAttribute(mma_gemm<0, true,  true >, cudaFuncAttributeMaxDynamicSharedMemorySize, SMEM_BYTES);
    cudaFuncSetAttribute(mma_gemm<2, false, true >, cudaFuncAttributeMaxDynamicSharedMemorySize, SMEM_BYTES);

    reset_kernel<<<1, 32>>>(cnt);

    // weight transpose + fp16 convert (in-graph)
    dim3 tb(32, 8);
    transpose_h<<<dim3(MLPH/32, H/32, 1),    tb>>>(w1,  w1t, H,    MLPH);
    transpose_h<<<dim3(H/32,    MLPH/32, 1), tb>>>(w2,  w2t, MLPH, H);
    transpose_h<<<dim3(EXPH/32, H/32, NEXP), tb>>>(ew1, e1t, H,    EXPH);
    transpose_h<<<dim3(H/32, EXPH/32, NEXP), tb>>>(ew2, e2t, EXPH, H);

    // ResMLP block
    ln_kernel<<<NT, 256>>>(x, ln1g, ln1b, xn, nullptr, 0);
    mma_gemm<0, false, false><<<dim3(MLPH/256, NT/128), 256, SMEM_BYTES>>>(
        xn, H, 0,  w1t, H, 0,  h1, MLPH, 0,  b1, 0,
        nullptr, nullptr, 0, nullptr, NT, H);
    mma_gemm<1, false, false><<<dim3(H/256, NT/128), 256, SMEM_BYTES>>>(
        h1, MLPH, 0,  w2t, MLPH, 0,  hh, H, 0,  b2, 0,
        x, nullptr, 0, nullptr, NT, MLPH);
    ln_kernel<<<NT, 256>>>(hh, ln2g, ln2b, x2h, x2f, 1);

    // MoE (router on exact fp32 x2)
    router_kernel<<<(NT + 3) / 4, 128>>>(x2f, rw, cnt, tok, slot, wgt, NT);
    mma_gemm<0, true, true><<<dim3(EXPH/256, NT/128, NEXP), 256, SMEM_BYTES>>>(
        x2h, H, 0,  e1t, H, (long)EXPH * H,  he, EXPH, (long)NT * EXPH,
        eb1, EXPH, nullptr, tok, NT, cnt, NT, H);
    mma_gemm<2, false, true><<<dim3(H/256, NT/128, NEXP), 256, SMEM_BYTES>>>(
        he, EXPH, (long)NT * EXPH,  e2t, EXPH, (long)H * EXPH,  ye, H, (long)NT * H,
        eb2, H, nullptr, nullptr, 0, cnt, NT, EXPH);

    // combine + final LN + aux
    combine_ln_kernel<<<NT, 256>>>(ye, slot, wgt, lnfg, lnfb, out);
    if (out_size > NT * H)
        aux_kernel<<<1, 1>>>(cnt, out, (long)NT * H, 1.0f / (2.0f * NT));
}